// round 13
// baseline (speedup 1.0000x reference)
#include <cuda_runtime.h>
#include <math.h>

// ---------------------------------------------------------------------------
// Model1_11596411699487: 5x 4D conv (valid, stride 1) + ReLU, flatten,
// dense 1280->33 + ReLU, dense 33->2, softmax.
//
// Round 13 (= round 11 resubmit, infra failed): batch-last ([q][B]) layout
// for conv2..conv5 so warp lanes span the batch dimension -> fully coalesced
// loads/stores. conv1 stays spatial-major (verified) + one transpose kernel
// (de-risked to 32x8 blocks).
// ---------------------------------------------------------------------------

#define BATCH 256

// conv1 output (spatial-major, z padded to 16) and its batch-last transpose.
#define Q1 (3 * 15 * 15 * 15 * 16)
__device__ float g_h1 [BATCH * Q1];
__device__ float g_h1t[Q1 * BATCH];                 // [q][B]
__device__ float g_h2t[3 * 12 * 12 * 12 * 12 * BATCH];
__device__ float g_h3t[4 * 9 * 9 * 9 * 9 * BATCH];
__device__ float g_h4t[5 * 6 * 6 * 6 * 6 * BATCH];
__device__ float g_h5t[5 * 4 * 4 * 4 * 4 * BATCH];  // [1280][B], feeds head

// ---------------- spatial-major conv (conv1 only; verified path) -----------
template <int EXT, int ALIGN>
__device__ __forceinline__ void load_row(float* __restrict__ r,
                                         const float* __restrict__ p)
{
    constexpr int N4 = (ALIGN >= 4) ? EXT / 4 : 0;
    constexpr int R4 = EXT - 4 * N4;
    constexpr int N2 = (ALIGN >= 2) ? R4 / 2 : 0;
    constexpr int N1 = R4 - 2 * N2;
#pragma unroll
    for (int j = 0; j < N4; j++) {
        float4 v = *(const float4*)(p + 4 * j);
        r[4 * j + 0] = v.x; r[4 * j + 1] = v.y;
        r[4 * j + 2] = v.z; r[4 * j + 3] = v.w;
    }
#pragma unroll
    for (int j = 0; j < N2; j++) {
        float2 v = *(const float2*)(p + 4 * N4 + 2 * j);
        r[4 * N4 + 2 * j + 0] = v.x;
        r[4 * N4 + 2 * j + 1] = v.y;
    }
#pragma unroll
    for (int j = 0; j < N1; j++)
        r[4 * N4 + 2 * N2 + j] = p[4 * N4 + 2 * N2 + j];
}

template <int EXT, int ALIGN>
__device__ __forceinline__ void store_row(float* __restrict__ p,
                                          const float* __restrict__ r)
{
    constexpr int N4 = (ALIGN >= 4) ? EXT / 4 : 0;
    constexpr int R4 = EXT - 4 * N4;
    constexpr int N2 = (ALIGN >= 2) ? R4 / 2 : 0;
    constexpr int N1 = R4 - 2 * N2;
#pragma unroll
    for (int j = 0; j < N4; j++) {
        float4 v;
        v.x = r[4 * j + 0]; v.y = r[4 * j + 1];
        v.z = r[4 * j + 2]; v.w = r[4 * j + 3];
        *(float4*)(p + 4 * j) = v;
    }
#pragma unroll
    for (int j = 0; j < N2; j++) {
        float2 v;
        v.x = r[4 * N4 + 2 * j + 0];
        v.y = r[4 * N4 + 2 * j + 1];
        *(float2*)(p + 4 * N4 + 2 * j) = v;
    }
#pragma unroll
    for (int j = 0; j < N1; j++)
        p[4 * N4 + 2 * N2 + j] = r[4 * N4 + 2 * N2 + j];
}

template <int Cin, int Cout, int Sin, int K,
          int PSin, int PSout, int ALIGN, int OALIGN>
__global__ void __launch_bounds__(128)
conv4d_relu_kernel(const float* __restrict__ in,
                   const float* __restrict__ wt,
                   const float* __restrict__ bias,
                   float* __restrict__ out)
{
    constexpr int Sout = Sin - K + 1;
    constexpr int WSZ  = Cout * Cin * K * K * K * K;
    constexpr int NPOS = Sout * Sout * Sout;

    __shared__ float sw[WSZ];
    __shared__ float sb[Cout];
    for (int i = threadIdx.x; i < WSZ; i += blockDim.x) sw[i] = wt[i];
    if (threadIdx.x < Cout) sb[threadIdx.x] = bias[threadIdx.x];
    __syncthreads();

    int tid = blockIdx.x * blockDim.x + threadIdx.x;
    if (tid >= BATCH * NPOS) return;

    int y0 = tid % Sout;
    int t1 = tid / Sout;
    int x0 = t1 % Sout;
    int t2 = t1 / Sout;
    int w0 = t2 % Sout;
    int b  = t2 / Sout;

    float acc[Cout * Sout];
#pragma unroll
    for (int c = 0; c < Cout; c++)
#pragma unroll
        for (int z = 0; z < Sout; z++) acc[c * Sout + z] = sb[c];

#pragma unroll 1
    for (int ci = 0; ci < Cin; ci++) {
#pragma unroll 1
        for (int kw = 0; kw < K; kw++) {
#pragma unroll 1
            for (int kx = 0; kx < K; kx++) {
                const float* base = in +
                    (size_t)((((b * Cin + ci) * Sin + (w0 + kw)) * Sin + (x0 + kx)) * Sin
                             + y0) * PSin;
                float r[K][Sin];
#pragma unroll
                for (int ky = 0; ky < K; ky++)
                    load_row<Sin, ALIGN>(r[ky], base + ky * PSin);

#pragma unroll
                for (int ky = 0; ky < K; ky++) {
#pragma unroll
                    for (int c = 0; c < Cout; c++) {
#pragma unroll
                        for (int kz = 0; kz < K; kz++) {
                            float w = sw[((((c * Cin + ci) * K + kw) * K + kx) * K + ky) * K + kz];
#pragma unroll
                            for (int z = 0; z < Sout; z++)
                                acc[c * Sout + z] += r[ky][z + kz] * w;
                        }
                    }
                }
            }
        }
    }

#pragma unroll
    for (int c = 0; c < Cout; c++) {
        float* op = out +
            (size_t)((((b * Cout + c) * Sout + w0) * Sout + x0) * Sout + y0) * PSout;
        float rr[Sout];
#pragma unroll
        for (int z = 0; z < Sout; z++) rr[z] = fmaxf(acc[c * Sout + z], 0.0f);
        store_row<Sout, OALIGN>(op, rr);
    }
}

// ---------------- transpose [B][Q] -> [Q][B] (32x8 block, 4-row loop) ------
__global__ void __launch_bounds__(256)
transpose_kernel(const float* __restrict__ in, float* __restrict__ out, int Q)
{
    __shared__ float tile[32][33];
    int qb = blockIdx.x * 32;
    int bb = blockIdx.y * 32;
#pragma unroll
    for (int rr = 0; rr < 32; rr += 8) {
        int qx = qb + threadIdx.x;
        int br = bb + threadIdx.y + rr;
        if (qx < Q)
            tile[threadIdx.y + rr][threadIdx.x] = in[(size_t)br * Q + qx];
    }
    __syncthreads();
#pragma unroll
    for (int rr = 0; rr < 32; rr += 8) {
        int qo = qb + threadIdx.y + rr;
        if (qo < Q)
            out[(size_t)qo * BATCH + bb + threadIdx.x] =
                tile[threadIdx.x][threadIdx.y + rr];
    }
}

// ---------------- batch-last vector helpers --------------------------------
template <int NB>
__device__ __forceinline__ void ldvec(float* __restrict__ d,
                                      const float* __restrict__ p)
{
    if (NB == 4) {
        float4 v = *(const float4*)p;
        d[0] = v.x; d[1] = v.y; d[2] = v.z; d[3] = v.w;
    } else if (NB == 2) {
        float2 v = *(const float2*)p;
        d[0] = v.x; d[1] = v.y;
    } else {
        d[0] = p[0];
    }
}
template <int NB>
__device__ __forceinline__ void stvec(float* __restrict__ p,
                                      const float* __restrict__ d)
{
    if (NB == 4) {
        float4 v; v.x = d[0]; v.y = d[1]; v.z = d[2]; v.w = d[3];
        *(float4*)p = v;
    } else if (NB == 2) {
        float2 v; v.x = d[0]; v.y = d[1];
        *(float2*)p = v;
    } else {
        p[0] = d[0];
    }
}

// ---------------- batch-last direct 4D conv + ReLU -------------------------
// in/out are [q][BATCH]. Thread owns (zg, w0,x0,y0) x NB batches; computes
// TZ z-outputs for all Cout channels. Warp lanes span consecutive batch
// groups -> every load/store is a contiguous 32*NB*4-byte warp access.
//   PSin: z-stride inside the input's q indexing (16 for h1t, else Sin).
template <int Cin, int Cout, int Sin, int K, int TZ, int NB, int PSin>
__global__ void __launch_bounds__(128)
conv4d_relu_bl_kernel(const float* __restrict__ in,
                      const float* __restrict__ wt,
                      const float* __restrict__ bias,
                      float* __restrict__ out)
{
    constexpr int Sout = Sin - K + 1;
    static_assert(Sout % TZ == 0, "TZ must divide Sout");
    constexpr int ZG   = Sout / TZ;
    constexpr int EXT  = TZ + K - 1;
    constexpr int BG   = BATCH / NB;
    constexpr int WSZ  = Cout * Cin * K * K * K * K;
    constexpr int NPOSZ = Sout * Sout * Sout * ZG;

    __shared__ float sw[WSZ];
    __shared__ float sb[Cout];
    for (int i = threadIdx.x; i < WSZ; i += blockDim.x) sw[i] = wt[i];
    if (threadIdx.x < Cout) sb[threadIdx.x] = bias[threadIdx.x];
    __syncthreads();

    int tid = blockIdx.x * 128 + threadIdx.x;
    int bg  = tid % BG;
    int pos = tid / BG;
    if (pos >= NPOSZ) return;

    int y0 = pos % Sout;
    int t1 = pos / Sout;
    int x0 = t1 % Sout;
    int t2 = t1 / Sout;
    int w0 = t2 % Sout;
    int zg = t2 / Sout;
    int z0 = zg * TZ;
    int b  = bg * NB;

    float acc[Cout * TZ * NB];
#pragma unroll
    for (int c = 0; c < Cout; c++) {
        float bv = sb[c];
#pragma unroll
        for (int t = 0; t < TZ; t++)
#pragma unroll
            for (int n = 0; n < NB; n++)
                acc[(c * TZ + t) * NB + n] = bv;
    }

#pragma unroll 1
    for (int ci = 0; ci < Cin; ci++) {
#pragma unroll 1
        for (int kw = 0; kw < K; kw++) {
#pragma unroll 1
            for (int kx = 0; kx < K; kx++) {
                int qsp = ((ci * Sin + (w0 + kw)) * Sin + (x0 + kx)) * Sin + y0;
#pragma unroll
                for (int ky = 0; ky < K; ky++) {
                    const float* p = in +
                        (size_t)((qsp + ky) * PSin + z0) * BATCH + b;
                    float r[EXT * NB];
#pragma unroll
                    for (int t = 0; t < EXT; t++)
                        ldvec<NB>(r + t * NB, p + (size_t)t * BATCH);

#pragma unroll
                    for (int c = 0; c < Cout; c++) {
#pragma unroll
                        for (int kz = 0; kz < K; kz++) {
                            float w = sw[((((c * Cin + ci) * K + kw) * K + kx) * K + ky) * K + kz];
#pragma unroll
                            for (int t = 0; t < TZ; t++)
#pragma unroll
                                for (int n = 0; n < NB; n++)
                                    acc[(c * TZ + t) * NB + n] +=
                                        r[(t + kz) * NB + n] * w;
                        }
                    }
                }
            }
        }
    }

#pragma unroll
    for (int c = 0; c < Cout; c++) {
#pragma unroll
        for (int t = 0; t < TZ; t++) {
            float rr[NB];
#pragma unroll
            for (int n = 0; n < NB; n++)
                rr[n] = fmaxf(acc[(c * TZ + t) * NB + n], 0.0f);
            int qo = (((c * Sout + w0) * Sout + x0) * Sout + y0) * Sout + z0 + t;
            stvec<NB>(out + (size_t)qo * BATCH + b, rr);
        }
    }
}

// ---------------- head: reads h5t [1280][B] --------------------------------
__global__ void __launch_bounds__(64)
head_kernel_t(const float* __restrict__ ht,
              const float* __restrict__ dw1, const float* __restrict__ db1,
              const float* __restrict__ dw2, const float* __restrict__ db2,
              float* __restrict__ out)
{
    int b = blockIdx.x;
    __shared__ float sh[1280];
    __shared__ float s1[33];

    for (int i = threadIdx.x; i < 1280; i += blockDim.x)
        sh[i] = ht[(size_t)i * BATCH + b];
    __syncthreads();

    int j = threadIdx.x;
    if (j < 33) {
        float s = db1[j];
        const float* wr = dw1 + j * 1280;
#pragma unroll 4
        for (int i = 0; i < 1280; i++) s += wr[i] * sh[i];
        s1[j] = fmaxf(s, 0.0f);
    }
    __syncthreads();

    if (threadIdx.x == 0) {
        float l0 = db2[0], l1 = db2[1];
        for (int jj = 0; jj < 33; jj++) {
            l0 += dw2[jj] * s1[jj];
            l1 += dw2[33 + jj] * s1[jj];
        }
        float m  = fmaxf(l0, l1);
        float e0 = expf(l0 - m);
        float e1 = expf(l1 - m);
        float inv = 1.0f / (e0 + e1);
        out[b * 2 + 0] = e0 * inv;
        out[b * 2 + 1] = e1 * inv;
    }
}

static inline int cdiv(int a, int b) { return (a + b - 1) / b; }

extern "C" void kernel_launch(void* const* d_in, const int* in_sizes, int n_in,
                              void* d_out, int out_size)
{
    const float* x   = (const float*)d_in[0];
    const float* w1  = (const float*)d_in[1];
    const float* b1  = (const float*)d_in[2];
    const float* w2  = (const float*)d_in[3];
    const float* b2  = (const float*)d_in[4];
    const float* w3  = (const float*)d_in[5];
    const float* b3  = (const float*)d_in[6];
    const float* w4  = (const float*)d_in[7];
    const float* b4  = (const float*)d_in[8];
    const float* w5  = (const float*)d_in[9];
    const float* b5  = (const float*)d_in[10];
    const float* dw1 = (const float*)d_in[11];
    const float* db1 = (const float*)d_in[12];
    const float* dw2 = (const float*)d_in[13];
    const float* db2 = (const float*)d_in[14];
    float* out = (float*)d_out;

    float *h1, *h1t, *h2t, *h3t, *h4t, *h5t;
    cudaGetSymbolAddress((void**)&h1,  g_h1);
    cudaGetSymbolAddress((void**)&h1t, g_h1t);
    cudaGetSymbolAddress((void**)&h2t, g_h2t);
    cudaGetSymbolAddress((void**)&h3t, g_h3t);
    cudaGetSymbolAddress((void**)&h4t, g_h4t);
    cudaGetSymbolAddress((void**)&h5t, g_h5t);

    const int T = 128;

    // conv1: 1->3, 18->15, k=4. Spatial-major (verified), out z-stride 16.
    conv4d_relu_kernel<1, 3, 18, 4, 18, 16, 2, 4>
        <<<cdiv(BATCH * 15 * 15 * 15, T), T>>>(x, w1, b1, h1);

    // transpose h1 [B][Q1] -> h1t [Q1][B]
    {
        dim3 tb(32, 8);
        dim3 tg(cdiv(Q1, 32), BATCH / 32);
        transpose_kernel<<<tg, tb>>>(h1, h1t, Q1);
    }

    // conv2: 3->3, 15->12, k=4. TZ=4 (ZG=3), NB=4, input z-stride 16.
    {
        int threads = (BATCH / 4) * 12 * 12 * 12 * 3;
        conv4d_relu_bl_kernel<3, 3, 15, 4, 4, 4, 16>
            <<<cdiv(threads, T), T>>>(h1t, w2, b2, h2t);
    }
    // conv3: 3->4, 12->9, k=4. TZ=3 (ZG=3), NB=4.
    {
        int threads = (BATCH / 4) * 9 * 9 * 9 * 3;
        conv4d_relu_bl_kernel<3, 4, 12, 4, 3, 4, 12>
            <<<cdiv(threads, T), T>>>(h2t, w3, b3, h3t);
    }
    // conv4: 4->5, 9->6, k=4. TZ=3 (ZG=2), NB=2.
    {
        int threads = (BATCH / 2) * 6 * 6 * 6 * 2;
        conv4d_relu_bl_kernel<4, 5, 9, 4, 3, 2, 9>
            <<<cdiv(threads, T), T>>>(h3t, w4, b4, h4t);
    }
    // conv5: 5->5, 6->4, k=3. TZ=4 (ZG=1), NB=1.
    {
        int threads = BATCH * 4 * 4 * 4;
        conv4d_relu_bl_kernel<5, 5, 6, 3, 4, 1, 6>
            <<<cdiv(threads, T), T>>>(h4t, w5, b5, h5t);
    }
    // head
    head_kernel_t<<<BATCH, 64>>>(h5t, dw1, db1, dw2, db2, out);
}